// round 1
// baseline (speedup 1.0000x reference)
#include <cuda_runtime.h>

#define TILE 128
#define KC   16
#define PAD  132      // k-major smem row stride in floats; 132*4 bytes is 16B-aligned per row
#define MAXN 100000

// Node-projection scratch (alloc-guard-safe __device__ globals): 2 x 51.2 MB
static __device__ float g_msrc[(size_t)MAXN * 128];
static __device__ float g_mdst[(size_t)MAXN * 128];

// ---------------- packed f32x2 helpers (sm_103a FFMA2 path) ----------------
__device__ __forceinline__ unsigned long long pack2(float lo, float hi) {
    unsigned long long r;
    asm("mov.b64 %0, {%1, %2};" : "=l"(r) : "f"(lo), "f"(hi));
    return r;
}
__device__ __forceinline__ void unpack2(unsigned long long v, float& lo, float& hi) {
    asm("mov.b64 {%0, %1}, %2;" : "=f"(lo), "=f"(hi) : "l"(v));
}
__device__ __forceinline__ void ffma2(unsigned long long& d, unsigned long long a,
                                      unsigned long long b) {
    asm("fma.rn.f32x2 %0, %1, %2, %0;" : "+l"(d) : "l"(a), "l"(b));
}

// Load a [KC x 128] K-chunk transposed into dst[k][row] (row stride PAD).
// src is row-major [rows_total x 128]; out-of-range rows are zero-filled.
__device__ __forceinline__ void load_tile_T(float* dst, const float* __restrict__ src,
                                            long row0, long rows_total, int kc) {
    int tid = threadIdx.x;
#pragma unroll
    for (int q = 0; q < 2; q++) {
        int f   = tid * 2 + q;        // 0..511 float4 slots (128 rows x 4 float4)
        int row = f >> 2;
        int k4  = (f & 3) << 2;
        float4 v = make_float4(0.f, 0.f, 0.f, 0.f);
        long gr = row0 + row;
        if (gr < rows_total)
            v = *(const float4*)(src + (size_t)gr * 128 + kc + k4);
        dst[(k4 + 0) * PAD + row] = v.x;
        dst[(k4 + 1) * PAD + row] = v.y;
        dst[(k4 + 2) * PAD + row] = v.z;
        dst[(k4 + 3) * PAD + row] = v.w;
    }
}

// One K-chunk of the 128x128 tile GEMM.
// acc[ip][j]: packed pair of rows (2ip, 2ip+1) x 8 output columns per thread.
__device__ __forceinline__ void mma_chunk(unsigned long long acc[4][8],
                                          const float* A, const float* B,
                                          int tx, int ty) {
#pragma unroll
    for (int k = 0; k < KC; k++) {
        const float* ar = A + k * PAD + ty * 8;
        ulonglong2 a01 = *(const ulonglong2*)(ar);       // rows 0,1 | 2,3 packed
        ulonglong2 a23 = *(const ulonglong2*)(ar + 4);   // rows 4,5 | 6,7 packed
        const float* br = B + k * PAD + tx * 8;
        float4 w0 = *(const float4*)(br);
        float4 w1 = *(const float4*)(br + 4);
        unsigned long long aa[4] = {a01.x, a01.y, a23.x, a23.y};
        unsigned long long bb[8];
        bb[0] = pack2(w0.x, w0.x); bb[1] = pack2(w0.y, w0.y);
        bb[2] = pack2(w0.z, w0.z); bb[3] = pack2(w0.w, w0.w);
        bb[4] = pack2(w1.x, w1.x); bb[5] = pack2(w1.y, w1.y);
        bb[6] = pack2(w1.z, w1.z); bb[7] = pack2(w1.w, w1.w);
#pragma unroll
        for (int ip = 0; ip < 4; ip++)
#pragma unroll
            for (int j = 0; j < 8; j++)
                ffma2(acc[ip][j], aa[ip], bb[j]);
    }
}

// ---------------- Kernel A: node projections (feat @ w^T [+ b1]) ----------------
__global__ void __launch_bounds__(256, 2)
node_proj_kernel(const float* __restrict__ feat, const float* __restrict__ w,
                 const float* __restrict__ bias, int which, int nrows) {
    __shared__ float As[KC * PAD];
    __shared__ float Bs[KC * PAD];
    float* outp = which ? g_mdst : g_msrc;

    int tid = threadIdx.x, tx = tid & 15, ty = tid >> 4;
    long r0 = (long)blockIdx.x * TILE;

    unsigned long long acc[4][8];
#pragma unroll
    for (int ip = 0; ip < 4; ip++)
#pragma unroll
        for (int j = 0; j < 8; j++) acc[ip][j] = 0ull;

    for (int kc = 0; kc < 128; kc += KC) {
        __syncthreads();
        load_tile_T(As, feat, r0, nrows, kc);
        load_tile_T(Bs, w, 0, 128, kc);
        __syncthreads();
        mma_chunk(acc, As, Bs, tx, ty);
    }

    float bv[8] = {0.f, 0.f, 0.f, 0.f, 0.f, 0.f, 0.f, 0.f};
    if (bias) {
        float4 t0 = *(const float4*)(bias + tx * 8);
        float4 t1 = *(const float4*)(bias + tx * 8 + 4);
        bv[0] = t0.x; bv[1] = t0.y; bv[2] = t0.z; bv[3] = t0.w;
        bv[4] = t1.x; bv[5] = t1.y; bv[6] = t1.z; bv[7] = t1.w;
    }

#pragma unroll
    for (int ip = 0; ip < 4; ip++) {
        float lo[8], hi[8];
#pragma unroll
        for (int j = 0; j < 8; j++) {
            unpack2(acc[ip][j], lo[j], hi[j]);
            lo[j] += bv[j]; hi[j] += bv[j];
        }
        long r = r0 + ty * 8 + 2 * ip;
        if (r < nrows) {
            float* p = outp + (size_t)r * 128 + tx * 8;
            *(float4*)p       = make_float4(lo[0], lo[1], lo[2], lo[3]);
            *(float4*)(p + 4) = make_float4(lo[4], lo[5], lo[6], lo[7]);
        }
        if (r + 1 < nrows) {
            float* p = outp + (size_t)(r + 1) * 128 + tx * 8;
            *(float4*)p       = make_float4(hi[0], hi[1], hi[2], hi[3]);
            *(float4*)(p + 4) = make_float4(hi[4], hi[5], hi[6], hi[7]);
        }
    }
}

// ---------------- Kernel B: fused edge GEMM1 + gather + SiLU + GEMM2 + LN ----------------
__global__ void __launch_bounds__(256, 2)
edge_fused_kernel(const float* __restrict__ efeat,
                  const int* __restrict__ src_idx, const int* __restrict__ dst_idx,
                  const float* __restrict__ w1, const float* __restrict__ w2,
                  const float* __restrict__ b2, const float* __restrict__ gamma,
                  const float* __restrict__ beta, float* __restrict__ out, int E) {
    extern __shared__ float smem[];
    float* Xs   = smem;                          // [128][PAD]  (h-major: Xs[h][e])
    float* Abuf = smem + TILE * PAD;             // [KC][PAD]
    float* Bbuf = Abuf + KC * PAD;               // [KC][PAD]
    __shared__ int sidx[TILE];
    __shared__ int didx[TILE];

    int tid = threadIdx.x, tx = tid & 15, ty = tid >> 4;
    long e0 = (long)blockIdx.x * TILE;

    if (tid < TILE) {
        long e = e0 + tid;
        sidx[tid] = (e < E) ? src_idx[e] : 0;
        didx[tid] = (e < E) ? dst_idx[e] : 0;
    }

    unsigned long long acc[4][8];
#pragma unroll
    for (int ip = 0; ip < 4; ip++)
#pragma unroll
        for (int j = 0; j < 8; j++) acc[ip][j] = 0ull;

    // ---- GEMM1: efeat @ w1^T ----
    for (int kc = 0; kc < 128; kc += KC) {
        __syncthreads();
        load_tile_T(Abuf, efeat, e0, E, kc);
        load_tile_T(Bbuf, w1, 0, 128, kc);
        __syncthreads();
        mma_chunk(acc, Abuf, Bbuf, tx, ty);
    }

    // ---- gather node projections, add, SiLU ----
    float v[8][8];
#pragma unroll
    for (int ip = 0; ip < 4; ip++)
#pragma unroll
        for (int j = 0; j < 8; j++)
            unpack2(acc[ip][j], v[2 * ip][j], v[2 * ip + 1][j]);

#pragma unroll
    for (int i = 0; i < 8; i++) {
        int el = ty * 8 + i;
        size_t s = (size_t)sidx[el];
        size_t d = (size_t)didx[el];
        const float* ps = g_msrc + s * 128 + tx * 8;
        const float* pd = g_mdst + d * 128 + tx * 8;
        float4 s0 = *(const float4*)ps,       s1 = *(const float4*)(ps + 4);
        float4 d0 = *(const float4*)pd,       d1 = *(const float4*)(pd + 4);
        v[i][0] += s0.x + d0.x; v[i][1] += s0.y + d0.y;
        v[i][2] += s0.z + d0.z; v[i][3] += s0.w + d0.w;
        v[i][4] += s1.x + d1.x; v[i][5] += s1.y + d1.y;
        v[i][6] += s1.z + d1.z; v[i][7] += s1.w + d1.w;
#pragma unroll
        for (int j = 0; j < 8; j++) {
            float x = v[i][j];
            v[i][j] = x / (1.f + __expf(-x));
        }
    }

    // stage X^T into smem: Xs[h][e], float4 along e
#pragma unroll
    for (int j = 0; j < 8; j++) {
        int h = tx * 8 + j;
        float* row = Xs + h * PAD + ty * 8;
        *(float4*)row       = make_float4(v[0][j], v[1][j], v[2][j], v[3][j]);
        *(float4*)(row + 4) = make_float4(v[4][j], v[5][j], v[6][j], v[7][j]);
    }

    // ---- GEMM2: silu(X) @ w2^T ----
#pragma unroll
    for (int ip = 0; ip < 4; ip++)
#pragma unroll
        for (int j = 0; j < 8; j++) acc[ip][j] = 0ull;

    for (int hc = 0; hc < 128; hc += KC) {
        __syncthreads();                 // also orders Xs stores before Xs reads (hc==0)
        load_tile_T(Bbuf, w2, 0, 128, hc);
        __syncthreads();
        mma_chunk(acc, Xs + hc * PAD, Bbuf, tx, ty);
    }

    // ---- epilogue: +b2, LayerNorm(128) across the 16-thread half-warp row group ----
    float b2r[8], gr[8], br[8];
    {
        float4 t0 = *(const float4*)(b2 + tx * 8);
        float4 t1 = *(const float4*)(b2 + tx * 8 + 4);
        b2r[0] = t0.x; b2r[1] = t0.y; b2r[2] = t0.z; b2r[3] = t0.w;
        b2r[4] = t1.x; b2r[5] = t1.y; b2r[6] = t1.z; b2r[7] = t1.w;
        float4 g0 = *(const float4*)(gamma + tx * 8);
        float4 g1 = *(const float4*)(gamma + tx * 8 + 4);
        gr[0] = g0.x; gr[1] = g0.y; gr[2] = g0.z; gr[3] = g0.w;
        gr[4] = g1.x; gr[5] = g1.y; gr[6] = g1.z; gr[7] = g1.w;
        float4 bb0 = *(const float4*)(beta + tx * 8);
        float4 bb1 = *(const float4*)(beta + tx * 8 + 4);
        br[0] = bb0.x; br[1] = bb0.y; br[2] = bb0.z; br[3] = bb0.w;
        br[4] = bb1.x; br[5] = bb1.y; br[6] = bb1.z; br[7] = bb1.w;
    }

#pragma unroll
    for (int ip = 0; ip < 4; ip++)
#pragma unroll
        for (int j = 0; j < 8; j++)
            unpack2(acc[ip][j], v[2 * ip][j], v[2 * ip + 1][j]);

#pragma unroll
    for (int i = 0; i < 8; i++) {
        float s1 = 0.f, s2 = 0.f;
#pragma unroll
        for (int j = 0; j < 8; j++) {
            float y = v[i][j] + b2r[j];
            v[i][j] = y;
            s1 += y;
            s2 += y * y;
        }
#pragma unroll
        for (int m = 8; m >= 1; m >>= 1) {
            s1 += __shfl_xor_sync(0xffffffffu, s1, m, 16);
            s2 += __shfl_xor_sync(0xffffffffu, s2, m, 16);
        }
        float mean = s1 * (1.f / 128.f);
        float var  = s2 * (1.f / 128.f) - mean * mean;
        float inv  = rsqrtf(var + 1e-5f);
        long e = e0 + ty * 8 + i;
        if (e < E) {
            float o[8];
#pragma unroll
            for (int j = 0; j < 8; j++)
                o[j] = (v[i][j] - mean) * inv * gr[j] + br[j];
            float* p = out + (size_t)e * 128 + tx * 8;
            *(float4*)p       = make_float4(o[0], o[1], o[2], o[3]);
            *(float4*)(p + 4) = make_float4(o[4], o[5], o[6], o[7]);
        }
    }
}

// ---------------- launcher ----------------
extern "C" void kernel_launch(void* const* d_in, const int* in_sizes, int n_in,
                              void* d_out, int out_size) {
    const float* efeat    = (const float*)d_in[0];
    const float* src_feat = (const float*)d_in[1];
    const float* dst_feat = (const float*)d_in[2];
    const int*   src_idx  = (const int*)d_in[3];
    const int*   dst_idx  = (const int*)d_in[4];
    const float* w_ef     = (const float*)d_in[5];
    const float* w_src    = (const float*)d_in[6];
    const float* w_dst    = (const float*)d_in[7];
    const float* b1       = (const float*)d_in[8];
    const float* w2       = (const float*)d_in[9];
    const float* b2       = (const float*)d_in[10];
    const float* gamma    = (const float*)d_in[11];
    const float* beta     = (const float*)d_in[12];

    int E  = in_sizes[3];
    int Nn = in_sizes[1] / 128;

    const int edge_smem = (TILE + 2 * KC) * PAD * (int)sizeof(float);  // 84480 B
    cudaFuncSetAttribute(edge_fused_kernel,
                         cudaFuncAttributeMaxDynamicSharedMemorySize, edge_smem);

    int nb = (Nn + TILE - 1) / TILE;
    node_proj_kernel<<<nb, 256>>>(src_feat, w_src, nullptr, 0, Nn);
    node_proj_kernel<<<nb, 256>>>(dst_feat, w_dst, b1,      1, Nn);

    int eb = (E + TILE - 1) / TILE;
    edge_fused_kernel<<<eb, 256, edge_smem>>>(efeat, src_idx, dst_idx, w_ef, w2,
                                              b2, gamma, beta, (float*)d_out, E);
}

// round 3
// speedup vs baseline: 1.5101x; 1.5101x over previous
#include <cuda_runtime.h>

#define MAXN 100000
#define STR  132                 // smem row stride in 32-bit words
#define TELEM (128 * STR)        // words per 128x128 padded tile

static __device__ float g_msrc[(size_t)MAXN * 128];
static __device__ float g_mdst[(size_t)MAXN * 128];

// ---------------- helpers ----------------
__device__ __forceinline__ unsigned smem_u32(const void* p) {
    unsigned a;
    asm("{ .reg .u64 t; cvta.to.shared.u64 t, %1; cvt.u32.u64 %0, t; }" : "=r"(a) : "l"(p));
    return a;
}
__device__ __forceinline__ unsigned f2tf(float x) {
    unsigned r;
    asm("cvt.rna.tf32.f32 %0, %1;" : "=r"(r) : "f"(x));
    return r;
}
__device__ __forceinline__ void mma_tf32(float d[4], const unsigned a[4], const unsigned b[2]) {
    asm volatile(
        "mma.sync.aligned.m16n8k8.row.col.f32.tf32.tf32.f32 "
        "{%0,%1,%2,%3}, {%4,%5,%6,%7}, {%8,%9}, {%0,%1,%2,%3};"
        : "+f"(d[0]), "+f"(d[1]), "+f"(d[2]), "+f"(d[3])
        : "r"(a[0]), "r"(a[1]), "r"(a[2]), "r"(a[3]), "r"(b[0]), "r"(b[1]));
}

// async-load a [128 x 128] f32 tile into padded smem [128][STR]; OOB rows zero-filled
__device__ __forceinline__ void load_tile_async(float* As, const float* __restrict__ g,
                                                long row0, long rows, int tid) {
    unsigned sbase = smem_u32(As);
#pragma unroll
    for (int i = 0; i < 16; i++) {
        int idx = i * 256 + tid;
        int row = idx >> 5, c16 = idx & 31;
        unsigned dst = sbase + (unsigned)(row * STR + c16 * 4) * 4u;
        long gr = row0 + row;
        const float* src = g + (size_t)(gr < rows ? gr : 0) * 128 + c16 * 4;
        unsigned sz = (gr < rows) ? 16u : 0u;
        asm volatile("cp.async.cg.shared.global [%0], [%1], 16, %2;"
                     :: "r"(dst), "l"(src), "r"(sz));
    }
    asm volatile("cp.async.commit_group;" ::: "memory");
}

// stage a [128 x 128] weight matrix into smem, converted to tf32 bits
__device__ __forceinline__ void stage_w_tf32(unsigned* Ws, const float* __restrict__ w, int tid) {
#pragma unroll
    for (int i = 0; i < 16; i++) {
        int j4 = i * 256 + tid;          // 4096 float4 chunks
        int n  = j4 >> 5, k4 = (j4 & 31) * 4;
        float4 v = *(const float4*)(w + (size_t)n * 128 + k4);
        unsigned* p = Ws + n * STR + k4;
        p[0] = f2tf(v.x); p[1] = f2tf(v.y); p[2] = f2tf(v.z); p[3] = f2tf(v.w);
    }
}

// warp GEMM: C[32x64] += A[32x128] * B[64x128]^T ; A rows at mbase, B rows (=out cols) at nbase
// CVT_A: A smem holds raw f32 (convert); else A already holds tf32 bit patterns
template <bool CVT_A>
__device__ __forceinline__ void warp_gemm(const float* As, const unsigned* Bs,
                                          int mbase, int nbase, int lane,
                                          float acc[2][8][4]) {
    int r = lane >> 2, c = lane & 3;
    const float*    ap = As + (mbase + r) * STR + c;
    const unsigned* bp = Bs + (nbase + r) * STR + c;
#pragma unroll
    for (int kk = 0; kk < 128; kk += 8) {
        unsigned a[2][4], b[8][2];
#pragma unroll
        for (int mi = 0; mi < 2; mi++) {
            const float* q = ap + mi * (16 * STR) + kk;
            float x0 = q[0], x1 = q[8 * STR], x2 = q[4], x3 = q[8 * STR + 4];
            if (CVT_A) {
                a[mi][0] = f2tf(x0); a[mi][1] = f2tf(x1);
                a[mi][2] = f2tf(x2); a[mi][3] = f2tf(x3);
            } else {
                a[mi][0] = __float_as_uint(x0); a[mi][1] = __float_as_uint(x1);
                a[mi][2] = __float_as_uint(x2); a[mi][3] = __float_as_uint(x3);
            }
        }
#pragma unroll
        for (int ni = 0; ni < 8; ni++) {
            const unsigned* q = bp + ni * (8 * STR) + kk;
            b[ni][0] = q[0]; b[ni][1] = q[4];
        }
#pragma unroll
        for (int mi = 0; mi < 2; mi++)
#pragma unroll
            for (int ni = 0; ni < 8; ni++)
                mma_tf32(acc[mi][ni], a[mi], b[ni]);
    }
}

// scatter C fragments into smem [row][STR] as f32
__device__ __forceinline__ void store_C(float* Cs, float acc[2][8][4],
                                        int mbase, int nbase, int lane) {
    int r = lane >> 2, c2 = (lane & 3) * 2;
#pragma unroll
    for (int mi = 0; mi < 2; mi++)
#pragma unroll
        for (int ni = 0; ni < 8; ni++) {
            int row = mbase + mi * 16 + r, col = nbase + ni * 8 + c2;
            *(float2*)(Cs + row * STR + col)           = make_float2(acc[mi][ni][0], acc[mi][ni][1]);
            *(float2*)(Cs + (row + 8) * STR + col)     = make_float2(acc[mi][ni][2], acc[mi][ni][3]);
        }
}

// ---------------- Kernel A: node projections via mma.sync ----------------
__global__ void __launch_bounds__(256)
node_proj_mma(const float* __restrict__ feat, const float* __restrict__ w,
              const float* __restrict__ bias, int which, int nrows) {
    extern __shared__ float smf[];
    float*    As = smf;
    unsigned* Ws = (unsigned*)(smf + TELEM);
    __shared__ float sbias[128];

    int tid = threadIdx.x, lane = tid & 31, wid = tid >> 5;
    int mbase = (wid >> 1) * 32, nbase = (wid & 1) * 64;
    long r0 = (long)blockIdx.x * 128;

    load_tile_async(As, feat, r0, nrows, tid);
    stage_w_tf32(Ws, w, tid);
    if (tid < 128) sbias[tid] = bias ? bias[tid] : 0.f;
    asm volatile("cp.async.wait_group 0;" ::: "memory");
    __syncthreads();

    float acc[2][8][4];
#pragma unroll
    for (int mi = 0; mi < 2; mi++)
#pragma unroll
        for (int ni = 0; ni < 8; ni++)
#pragma unroll
            for (int q = 0; q < 4; q++) acc[mi][ni][q] = 0.f;

    warp_gemm<true>(As, Ws, mbase, nbase, lane, acc);
    __syncthreads();
    store_C(As, acc, mbase, nbase, lane);
    __syncthreads();

    int e = tid >> 1, half = tid & 1;
    long gr = r0 + e;
    if (gr < nrows) {
        float* po = (which ? g_mdst : g_msrc) + (size_t)gr * 128 + half * 64;
        const float* xr = As + e * STR + half * 64;
        const float* bb = sbias + half * 64;
#pragma unroll
        for (int i = 0; i < 16; i++) {
            float4 v = *(const float4*)(xr + i * 4);
            v.x += bb[i * 4 + 0]; v.y += bb[i * 4 + 1];
            v.z += bb[i * 4 + 2]; v.w += bb[i * 4 + 3];
            *(float4*)(po + i * 4) = v;
        }
    }
}

// ---------------- Kernel B: persistent fused edge kernel ----------------
__global__ void __launch_bounds__(256)
edge_mma_kernel(const float* __restrict__ efeat,
                const int* __restrict__ src_idx, const int* __restrict__ dst_idx,
                const float* __restrict__ w1, const float* __restrict__ w2,
                const float* __restrict__ b2, const float* __restrict__ gamma,
                const float* __restrict__ beta, float* __restrict__ out,
                int E, int ntiles) {
    extern __shared__ float smf[];
    float*    As  = smf;                       // A tile / C scratch / X buffer
    unsigned* W1s = (unsigned*)(smf + TELEM);
    unsigned* W2s = (unsigned*)(smf + 2 * TELEM);
    __shared__ int   sidx[128], didx[128];
    __shared__ float sb2[128], sgm[128], sbt[128];

    int tid = threadIdx.x, lane = tid & 31, wid = tid >> 5;
    int mbase = (wid >> 1) * 32, nbase = (wid & 1) * 64;
    int e = tid >> 1, half = tid & 1;

    stage_w_tf32(W1s, w1, tid);
    stage_w_tf32(W2s, w2, tid);
    if (tid < 128) { sb2[tid] = b2[tid]; sgm[tid] = gamma[tid]; sbt[tid] = beta[tid]; }

    for (long t = blockIdx.x; t < ntiles; t += gridDim.x) {
        long e0 = t * 128;
        __syncthreads();                       // As free (prev iter fully consumed)
        load_tile_async(As, efeat, e0, E, tid);
        if (tid < 128) {
            long ge = e0 + tid;
            sidx[tid] = (ge < E) ? src_idx[ge] : 0;
            didx[tid] = (ge < E) ? dst_idx[ge] : 0;
        }
        asm volatile("cp.async.wait_group 0;" ::: "memory");
        __syncthreads();

        // ---- GEMM1: C1 = efeat_tile @ w1^T ----
        float acc[2][8][4];
#pragma unroll
        for (int mi = 0; mi < 2; mi++)
#pragma unroll
            for (int ni = 0; ni < 8; ni++)
#pragma unroll
                for (int q = 0; q < 4; q++) acc[mi][ni][q] = 0.f;
        warp_gemm<true>(As, W1s, mbase, nbase, lane, acc);
        __syncthreads();
        store_C(As, acc, mbase, nbase, lane);
        __syncthreads();

        // ---- epilogue1: gather + add + SiLU -> X (tf32 bits, in place) ----
        {
            int s = sidx[e], d = didx[e];
            const float4* ps = (const float4*)(g_msrc + (size_t)s * 128 + half * 64);
            const float4* pd = (const float4*)(g_mdst + (size_t)d * 128 + half * 64);
            float4* xw = (float4*)(As + e * STR + half * 64);
#pragma unroll
            for (int i = 0; i < 16; i++) {
                float4 x = xw[i], a = ps[i], b = pd[i];
                x.x += a.x + b.x; x.y += a.y + b.y;
                x.z += a.z + b.z; x.w += a.w + b.w;
                x.x = x.x / (1.f + __expf(-x.x));
                x.y = x.y / (1.f + __expf(-x.y));
                x.z = x.z / (1.f + __expf(-x.z));
                x.w = x.w / (1.f + __expf(-x.w));
                float4 o;
                o.x = __uint_as_float(f2tf(x.x)); o.y = __uint_as_float(f2tf(x.y));
                o.z = __uint_as_float(f2tf(x.z)); o.w = __uint_as_float(f2tf(x.w));
                xw[i] = o;
            }
        }
        __syncthreads();

        // ---- GEMM2: C2 = X @ w2^T ----
#pragma unroll
        for (int mi = 0; mi < 2; mi++)
#pragma unroll
            for (int ni = 0; ni < 8; ni++)
#pragma unroll
                for (int q = 0; q < 4; q++) acc[mi][ni][q] = 0.f;
        warp_gemm<false>(As, W2s, mbase, nbase, lane, acc);
        __syncthreads();
        store_C(As, acc, mbase, nbase, lane);
        __syncthreads();

        // ---- LayerNorm + store ----
        {
            const float* xr = As + e * STR + half * 64;
            const float* bb = sb2 + half * 64;
            float s1 = 0.f, s2 = 0.f;
#pragma unroll
            for (int i = 0; i < 16; i++) {
                float4 v = *(const float4*)(xr + i * 4);
                float y0 = v.x + bb[i * 4 + 0], y1 = v.y + bb[i * 4 + 1];
                float y2 = v.z + bb[i * 4 + 2], y3 = v.w + bb[i * 4 + 3];
                s1 += y0 + y1 + y2 + y3;
                s2 += y0 * y0 + y1 * y1 + y2 * y2 + y3 * y3;
            }
            s1 += __shfl_xor_sync(0xffffffffu, s1, 1);
            s2 += __shfl_xor_sync(0xffffffffu, s2, 1);
            float mean = s1 * (1.f / 128.f);
            float var  = s2 * (1.f / 128.f) - mean * mean;
            float inv  = rsqrtf(var + 1e-5f);
            long ge = e0 + e;
            if (ge < E) {
                float* po = out + (size_t)ge * 128 + half * 64;
                const float* gg = sgm + half * 64;
                const float* tt = sbt + half * 64;
#pragma unroll
                for (int i = 0; i < 16; i++) {
                    float4 v = *(const float4*)(xr + i * 4);
                    float4 o;
                    o.x = (v.x + bb[i*4+0] - mean) * inv * gg[i*4+0] + tt[i*4+0];
                    o.y = (v.y + bb[i*4+1] - mean) * inv * gg[i*4+1] + tt[i*4+1];
                    o.z = (v.z + bb[i*4+2] - mean) * inv * gg[i*4+2] + tt[i*4+2];
                    o.w = (v.w + bb[i*4+3] - mean) * inv * gg[i*4+3] + tt[i*4+3];
                    *(float4*)(po + i * 4) = o;
                }
            }
        }
    }
}

// ---------------- launcher ----------------
extern "C" void kernel_launch(void* const* d_in, const int* in_sizes, int n_in,
                              void* d_out, int out_size) {
    const float* efeat    = (const float*)d_in[0];
    const float* src_feat = (const float*)d_in[1];
    const float* dst_feat = (const float*)d_in[2];
    const int*   src_idx  = (const int*)d_in[3];
    const int*   dst_idx  = (const int*)d_in[4];
    const float* w_ef     = (const float*)d_in[5];
    const float* w_src    = (const float*)d_in[6];
    const float* w_dst    = (const float*)d_in[7];
    const float* b1       = (const float*)d_in[8];
    const float* w2       = (const float*)d_in[9];
    const float* b2       = (const float*)d_in[10];
    const float* gamma    = (const float*)d_in[11];
    const float* beta     = (const float*)d_in[12];

    int E  = in_sizes[3];
    int Nn = in_sizes[1] / 128;

    const int node_smem = 2 * TELEM * (int)sizeof(float);   // 135,168 B
    const int edge_smem = 3 * TELEM * (int)sizeof(float);   // 202,752 B
    cudaFuncSetAttribute(node_proj_mma,
                         cudaFuncAttributeMaxDynamicSharedMemorySize, node_smem);
    cudaFuncSetAttribute(edge_mma_kernel,
                         cudaFuncAttributeMaxDynamicSharedMemorySize, edge_smem);

    int nb = (Nn + 127) / 128;
    node_proj_mma<<<nb, 256, node_smem>>>(src_feat, w_src, nullptr, 0, Nn);
    node_proj_mma<<<nb, 256, node_smem>>>(dst_feat, w_dst, b1,      1, Nn);

    int ntiles = (E + 127) / 128;
    int nsm = 148;
    cudaDeviceGetAttribute(&nsm, cudaDevAttrMultiProcessorCount, 0);
    int grid = ntiles < nsm ? ntiles : nsm;
    edge_mma_kernel<<<grid, 256, edge_smem>>>(efeat, src_idx, dst_idx, w_ef, w2,
                                              b2, gamma, beta, (float*)d_out, E, ntiles);
}

// round 4
// speedup vs baseline: 2.1210x; 1.4045x over previous
#include <cuda_runtime.h>

#define MAXN 100000
#define STR  132                  // padded smem row stride (words); 132%32=4 -> conflict-free GEMM reads
#define TWORDS (128 * STR)        // words per 128x128 padded tile

static __device__ float g_msrc[(size_t)MAXN * 128];
static __device__ float g_mdst[(size_t)MAXN * 128];

// ---------------- helpers ----------------
__device__ __forceinline__ unsigned smem_u32(const void* p) {
    unsigned a;
    asm("{ .reg .u64 t; cvta.to.shared.u64 t, %1; cvt.u32.u64 %0, t; }" : "=r"(a) : "l"(p));
    return a;
}
__device__ __forceinline__ unsigned f2tf(float x) {
    unsigned r;
    asm("cvt.rna.tf32.f32 %0, %1;" : "=r"(r) : "f"(x));
    return r;
}
__device__ __forceinline__ void mma_tf32(float d[4], const unsigned a[4], const unsigned b[2]) {
    asm volatile(
        "mma.sync.aligned.m16n8k8.row.col.f32.tf32.tf32.f32 "
        "{%0,%1,%2,%3}, {%4,%5,%6,%7}, {%8,%9}, {%0,%1,%2,%3};"
        : "+f"(d[0]), "+f"(d[1]), "+f"(d[2]), "+f"(d[3])
        : "r"(a[0]), "r"(a[1]), "r"(a[2]), "r"(a[3]), "r"(b[0]), "r"(b[1]));
}

// async-load a [128 x 128] f32 tile into padded smem [128][STR]; OOB rows zero-filled (512 thr)
__device__ __forceinline__ void load_tile_async(float* As, const float* __restrict__ g,
                                                long row0, long rows, int tid) {
    unsigned sbase = smem_u32(As);
#pragma unroll
    for (int i = 0; i < 8; i++) {
        int idx = i * 512 + tid;                 // 4096 16B chunks
        int row = idx >> 5, c16 = idx & 31;
        unsigned dst = sbase + (unsigned)(row * STR + c16 * 4) * 4u;
        long gr = row0 + row;
        const float* src = g + (size_t)(gr < rows ? gr : 0) * 128 + c16 * 4;
        unsigned sz = (gr < rows) ? 16u : 0u;
        asm volatile("cp.async.cg.shared.global [%0], [%1], 16, %2;"
                     :: "r"(dst), "l"(src), "r"(sz));
    }
    asm volatile("cp.async.commit_group;" ::: "memory");
}

// stage a [128 x 128] weight matrix into padded smem as tf32 bits (512 thr)
__device__ __forceinline__ void stage_w_tf32(unsigned* Ws, const float* __restrict__ w, int tid) {
#pragma unroll
    for (int i = 0; i < 8; i++) {
        int j4 = i * 512 + tid;                  // 4096 float4 chunks
        int n  = j4 >> 5, k4 = (j4 & 31) * 4;
        float4 v = *(const float4*)(w + (size_t)n * 128 + k4);
        unsigned* p = Ws + n * STR + k4;
        p[0] = f2tf(v.x); p[1] = f2tf(v.y); p[2] = f2tf(v.z); p[3] = f2tf(v.w);
    }
}

// warp GEMM: C[32x32] += A[32x128] * B[32x128]^T   (16-warp layout)
template <bool CVT_A>
__device__ __forceinline__ void warp_gemm32(const float* As, const unsigned* Bs,
                                            int mbase, int nbase, int lane,
                                            float acc[2][4][4]) {
    int r = lane >> 2, c = lane & 3;
    const float*    ap = As + (mbase + r) * STR + c;
    const unsigned* bp = Bs + (nbase + r) * STR + c;
#pragma unroll
    for (int kk = 0; kk < 128; kk += 8) {
        unsigned a[2][4], b[4][2];
#pragma unroll
        for (int mi = 0; mi < 2; mi++) {
            const float* p = ap + mi * (16 * STR) + kk;
            float x0 = p[0], x1 = p[8 * STR], x2 = p[4], x3 = p[8 * STR + 4];
            if (CVT_A) {
                a[mi][0] = f2tf(x0); a[mi][1] = f2tf(x1);
                a[mi][2] = f2tf(x2); a[mi][3] = f2tf(x3);
            } else {
                a[mi][0] = __float_as_uint(x0); a[mi][1] = __float_as_uint(x1);
                a[mi][2] = __float_as_uint(x2); a[mi][3] = __float_as_uint(x3);
            }
        }
#pragma unroll
        for (int ni = 0; ni < 4; ni++) {
            const unsigned* pb = bp + ni * (8 * STR) + kk;
            b[ni][0] = pb[0]; b[ni][1] = pb[4];
        }
#pragma unroll
        for (int mi = 0; mi < 2; mi++)
#pragma unroll
            for (int ni = 0; ni < 4; ni++)
                mma_tf32(acc[mi][ni], a[mi], b[ni]);
    }
}

__device__ __forceinline__ void store_C32(float* Cs, float acc[2][4][4],
                                          int mbase, int nbase, int lane) {
    int r = lane >> 2, c2 = (lane & 3) * 2;
#pragma unroll
    for (int mi = 0; mi < 2; mi++)
#pragma unroll
        for (int ni = 0; ni < 4; ni++) {
            int row = mbase + mi * 16 + r, col = nbase + ni * 8 + c2;
            *(float2*)(Cs + row * STR + col)       = make_float2(acc[mi][ni][0], acc[mi][ni][1]);
            *(float2*)(Cs + (row + 8) * STR + col) = make_float2(acc[mi][ni][2], acc[mi][ni][3]);
        }
}

// ---------------- Kernel A: persistent node projections ----------------
__global__ void __launch_bounds__(512, 1)
node_proj2(const float* __restrict__ feat, const float* __restrict__ w,
           const float* __restrict__ bias, int which, int nrows, int ntiles) {
    extern __shared__ float smf[];
    float*    As = smf;
    unsigned* Ws = (unsigned*)(smf + TWORDS);
    float*    Cs = smf + 2 * TWORDS;
    __shared__ float sbias[128];

    int tid = threadIdx.x, lane = tid & 31, wid = tid >> 5;
    int mbase = (wid >> 2) * 32, nbase = (wid & 3) * 32;
    int e = tid >> 2, q = tid & 3;

    stage_w_tf32(Ws, w, tid);
    if (tid < 128) sbias[tid] = bias ? bias[tid] : 0.f;

    long t = blockIdx.x;
    if (t < ntiles) load_tile_async(As, feat, t * 128, nrows, tid);
    __syncthreads();

    float* outp = which ? g_mdst : g_msrc;

    for (; t < ntiles; t += gridDim.x) {
        asm volatile("cp.async.wait_group 0;" ::: "memory");
        __syncthreads();

        float acc[2][4][4];
#pragma unroll
        for (int mi = 0; mi < 2; mi++)
#pragma unroll
            for (int ni = 0; ni < 4; ni++)
#pragma unroll
                for (int k = 0; k < 4; k++) acc[mi][ni][k] = 0.f;
        warp_gemm32<true>(As, Ws, mbase, nbase, lane, acc);
        __syncthreads();                      // A reads done

        long nt = t + gridDim.x;
        if (nt < ntiles) load_tile_async(As, feat, nt * 128, nrows, tid);

        store_C32(Cs, acc, mbase, nbase, lane);
        __syncthreads();

        long gr = t * 128 + e;
        if (gr < nrows) {
            float* po = outp + (size_t)gr * 128;
            const float* rp = Cs + e * STR;
#pragma unroll
            for (int i = 0; i < 8; i++) {
                int k = q * 4 + i * 16;
                float4 v = *(const float4*)(rp + k);
                v.x += sbias[k + 0]; v.y += sbias[k + 1];
                v.z += sbias[k + 2]; v.w += sbias[k + 3];
                *(float4*)(po + k) = v;
            }
        }
    }
}

// ---------------- Kernel B: persistent fused edge kernel ----------------
__global__ void __launch_bounds__(512, 1)
edge_mma2(const float* __restrict__ efeat,
          const int* __restrict__ src_idx, const int* __restrict__ dst_idx,
          const float* __restrict__ w1, const float* __restrict__ w2,
          const float* __restrict__ b2f, const float* __restrict__ gammaf,
          const float* __restrict__ betaf, float* __restrict__ out,
          int E, int ntiles) {
    extern __shared__ float smf[];
    float*    As  = smf;
    unsigned* W1s = (unsigned*)(smf + TWORDS);
    unsigned* W2s = (unsigned*)(smf + 2 * TWORDS);
    __shared__ float sb2[128], sgm[128], sbt[128];
    __shared__ float red1[4][128], red2[4][128];

    int tid = threadIdx.x, lane = tid & 31, wid = tid >> 5;
    int r = lane >> 2, cc = lane & 3;
    int mbase = (wid >> 2) * 32, nbase = (wid & 3) * 32;
    int e = tid >> 2, q = tid & 3;

    stage_w_tf32(W1s, w1, tid);
    stage_w_tf32(W2s, w2, tid);
    if (tid < 128) { sb2[tid] = b2f[tid]; sgm[tid] = gammaf[tid]; sbt[tid] = betaf[tid]; }

    long t = blockIdx.x;
    float4 sv[8], dv[8];
    if (t < ntiles) {
        load_tile_async(As, efeat, t * 128, E, tid);
        long ge = t * 128 + e;
        int is = (ge < E) ? __ldg(src_idx + ge) : 0;
        int id = (ge < E) ? __ldg(dst_idx + ge) : 0;
        const float* ps = g_msrc + (size_t)is * 128;
        const float* pd = g_mdst + (size_t)id * 128;
#pragma unroll
        for (int i = 0; i < 8; i++) {
            sv[i] = __ldg((const float4*)(ps + q * 4 + i * 16));
            dv[i] = __ldg((const float4*)(pd + q * 4 + i * 16));
        }
    }
    __syncthreads();

    for (; t < ntiles; t += gridDim.x) {
        asm volatile("cp.async.wait_group 0;" ::: "memory");
        __syncthreads();

        // ---- GEMM1 (gather loads land during this) ----
        float acc[2][4][4];
#pragma unroll
        for (int mi = 0; mi < 2; mi++)
#pragma unroll
            for (int ni = 0; ni < 4; ni++)
#pragma unroll
                for (int k = 0; k < 4; k++) acc[mi][ni][k] = 0.f;
        warp_gemm32<true>(As, W1s, mbase, nbase, lane, acc);
        __syncthreads();
        store_C32(As, acc, mbase, nbase, lane);     // C1 into As (A dead)
        __syncthreads();

        // ---- epilogue1: + gather, SiLU, tf32 -> X in place ----
        {
            float* rowp = As + e * STR;
#pragma unroll
            for (int i = 0; i < 8; i++) {
                int k = q * 4 + i * 16;
                float4 x = *(const float4*)(rowp + k);
                x.x += sv[i].x + dv[i].x; x.y += sv[i].y + dv[i].y;
                x.z += sv[i].z + dv[i].z; x.w += sv[i].w + dv[i].w;
                x.x = x.x / (1.f + __expf(-x.x));
                x.y = x.y / (1.f + __expf(-x.y));
                x.z = x.z / (1.f + __expf(-x.z));
                x.w = x.w / (1.f + __expf(-x.w));
                float4 o;
                o.x = __uint_as_float(f2tf(x.x)); o.y = __uint_as_float(f2tf(x.y));
                o.z = __uint_as_float(f2tf(x.z)); o.w = __uint_as_float(f2tf(x.w));
                *(float4*)(rowp + k) = o;
            }
        }
        __syncthreads();

        // ---- GEMM2 ----
        float acc2[2][4][4];
#pragma unroll
        for (int mi = 0; mi < 2; mi++)
#pragma unroll
            for (int ni = 0; ni < 4; ni++)
#pragma unroll
                for (int k = 0; k < 4; k++) acc2[mi][ni][k] = 0.f;
        warp_gemm32<false>(As, W2s, mbase, nbase, lane, acc2);
        __syncthreads();                            // X reads done -> As free

        // ---- tail prefetch for next tile (overlaps LN + stores) ----
        long nt = t + gridDim.x;
        if (nt < ntiles) {
            load_tile_async(As, efeat, nt * 128, E, tid);
            long ge = nt * 128 + e;
            int is = (ge < E) ? __ldg(src_idx + ge) : 0;
            int id = (ge < E) ? __ldg(dst_idx + ge) : 0;
            const float* ps = g_msrc + (size_t)is * 128;
            const float* pd = g_mdst + (size_t)id * 128;
#pragma unroll
            for (int i = 0; i < 8; i++) {
                sv[i] = __ldg((const float4*)(ps + q * 4 + i * 16));
                dv[i] = __ldg((const float4*)(pd + q * 4 + i * 16));
            }
        }

        // ---- LayerNorm in fragment layout ----
        float s1[2][2], s2[2][2];
#pragma unroll
        for (int mi = 0; mi < 2; mi++)
#pragma unroll
            for (int h = 0; h < 2; h++) { s1[mi][h] = 0.f; s2[mi][h] = 0.f; }
#pragma unroll
        for (int mi = 0; mi < 2; mi++)
#pragma unroll
            for (int ni = 0; ni < 4; ni++) {
                int col0 = nbase + ni * 8 + cc * 2;
                float b0 = sb2[col0], b1 = sb2[col0 + 1];
                float y0 = acc2[mi][ni][0] + b0, y1 = acc2[mi][ni][1] + b1;
                float y2 = acc2[mi][ni][2] + b0, y3 = acc2[mi][ni][3] + b1;
                s1[mi][0] += y0 + y1; s2[mi][0] += y0 * y0 + y1 * y1;
                s1[mi][1] += y2 + y3; s2[mi][1] += y2 * y2 + y3 * y3;
            }
#pragma unroll
        for (int mi = 0; mi < 2; mi++)
#pragma unroll
            for (int h = 0; h < 2; h++) {
                s1[mi][h] += __shfl_xor_sync(0xffffffffu, s1[mi][h], 1);
                s1[mi][h] += __shfl_xor_sync(0xffffffffu, s1[mi][h], 2);
                s2[mi][h] += __shfl_xor_sync(0xffffffffu, s2[mi][h], 1);
                s2[mi][h] += __shfl_xor_sync(0xffffffffu, s2[mi][h], 2);
            }
        int nw = wid & 3;
        if (cc == 0) {
#pragma unroll
            for (int mi = 0; mi < 2; mi++)
#pragma unroll
                for (int h = 0; h < 2; h++) {
                    int row = mbase + mi * 16 + h * 8 + r;
                    red1[nw][row] = s1[mi][h];
                    red2[nw][row] = s2[mi][h];
                }
        }
        __syncthreads();

        long e0 = t * 128;
#pragma unroll
        for (int mi = 0; mi < 2; mi++)
#pragma unroll
            for (int h = 0; h < 2; h++) {
                int row = mbase + mi * 16 + h * 8 + r;
                float S1 = red1[0][row] + red1[1][row] + red1[2][row] + red1[3][row];
                float S2 = red2[0][row] + red2[1][row] + red2[2][row] + red2[3][row];
                float mean = S1 * (1.f / 128.f);
                float var  = S2 * (1.f / 128.f) - mean * mean;
                float inv  = rsqrtf(var + 1e-5f);
                long ge = e0 + row;
                if (ge < E) {
                    float* po = out + (size_t)ge * 128;
#pragma unroll
                    for (int ni = 0; ni < 4; ni++) {
                        int col0 = nbase + ni * 8 + cc * 2;
                        float b0 = sb2[col0], b1 = sb2[col0 + 1];
                        float ya = acc2[mi][ni][2 * h + 0] + b0;
                        float yb = acc2[mi][ni][2 * h + 1] + b1;
                        float oa = (ya - mean) * inv * sgm[col0]     + sbt[col0];
                        float ob = (yb - mean) * inv * sgm[col0 + 1] + sbt[col0 + 1];
                        *(float2*)(po + col0) = make_float2(oa, ob);
                    }
                }
            }
        __syncthreads();   // red arrays reusable next iter
    }
}

// ---------------- launcher ----------------
extern "C" void kernel_launch(void* const* d_in, const int* in_sizes, int n_in,
                              void* d_out, int out_size) {
    const float* efeat    = (const float*)d_in[0];
    const float* src_feat = (const float*)d_in[1];
    const float* dst_feat = (const float*)d_in[2];
    const int*   src_idx  = (const int*)d_in[3];
    const int*   dst_idx  = (const int*)d_in[4];
    const float* w_ef     = (const float*)d_in[5];
    const float* w_src    = (const float*)d_in[6];
    const float* w_dst    = (const float*)d_in[7];
    const float* b1       = (const float*)d_in[8];
    const float* w2       = (const float*)d_in[9];
    const float* b2       = (const float*)d_in[10];
    const float* gamma    = (const float*)d_in[11];
    const float* beta     = (const float*)d_in[12];

    int E  = in_sizes[3];
    int Nn = in_sizes[1] / 128;

    const int smem3 = 3 * TWORDS * (int)sizeof(float);   // 202,752 B
    cudaFuncSetAttribute(node_proj2,
                         cudaFuncAttributeMaxDynamicSharedMemorySize, smem3);
    cudaFuncSetAttribute(edge_mma2,
                         cudaFuncAttributeMaxDynamicSharedMemorySize, smem3);

    int nsm = 148;
    cudaDeviceGetAttribute(&nsm, cudaDevAttrMultiProcessorCount, 0);

    int ntilesN = (Nn + 127) / 128;
    int gridN = ntilesN < nsm ? ntilesN : nsm;
    node_proj2<<<gridN, 512, smem3>>>(src_feat, w_src, nullptr, 0, Nn, ntilesN);
    node_proj2<<<gridN, 512, smem3>>>(dst_feat, w_dst, b1,      1, Nn, ntilesN);

    int ntiles = (E + 127) / 128;
    int gridE = ntiles < nsm ? ntiles : nsm;
    edge_mma2<<<gridE, 512, smem3>>>(efeat, src_idx, dst_idx, w_ef, w2,
                                     b2, gamma, beta, (float*)d_out, E, ntiles);
}